// round 17
// baseline (speedup 1.0000x reference)
#include <cuda_runtime.h>

#define NN 100000
#define DD 64
#define NE 1200000
#define NEH (NE / 2)

#define FC_BLOCKS   1563              /* ceil(NN/64) */
#define SP_BLOCKS   18750             /* NEH*8/256 */
#define ADD_BLOCKS  6250              /* NN*DD/4/256 */

// scratch: x1 = A1 @ all_emb  (25.6 MB, __device__ global per allocation rules)
__device__ float g_x1[NN * DD];

// ---------------- packed f32x2 helpers ----------------
__device__ __forceinline__ unsigned long long pk2(float lo, float hi) {
    unsigned long long r;
    asm("mov.b64 %0, {%1, %2};" : "=l"(r) : "f"(lo), "f"(hi));
    return r;
}
__device__ __forceinline__ void upk2(float& lo, float& hi, unsigned long long v) {
    asm("mov.b64 {%0, %1}, %2;" : "=f"(lo), "=f"(hi) : "l"(v));
}
__device__ __forceinline__ void ffma2(unsigned long long& d,
                                      unsigned long long a,
                                      unsigned long long b) {
    asm("fma.rn.f32x2 %0, %1, %2, %0;" : "+l"(d) : "l"(a), "l"(b));
}

__device__ __forceinline__ void red_add_v4(float* addr, float a, float b,
                                           float c, float d) {
    asm volatile("red.global.add.v4.f32 [%0], {%1, %2, %3, %4};"
                 :: "l"(addr), "f"(a), "f"(b), "f"(c), "f"(d)
                 : "memory");
}

__global__ void zero_kernel(float* __restrict__ p, int n4) {
    int i = blockIdx.x * blockDim.x + threadIdx.x;
    if (i < n4) ((float4*)p)[i] = make_float4(0.f, 0.f, 0.f, 0.f);
}

// R6-proven spmm body: TWO edges per thread (e, e+NE/2), 8 lanes/edge,
// 2 float4 per lane; unconditional parallel metadata; predicated gather+red.
__device__ __forceinline__ void
spmm_body(const float* __restrict__ x,
          const float* __restrict__ vals,
          const float* __restrict__ du,
          const int*   __restrict__ rows,
          const int*   __restrict__ cols,
          float*       __restrict__ out,
          float scale, unsigned blk) {
    unsigned gid = blk * 256 + threadIdx.x;
    unsigned e0  = gid >> 3;
    if (e0 >= NEH) return;
    unsigned e1   = e0 + NEH;
    unsigned lane = gid & 7u;

    float u0 = du[e0],  u1 = du[e1];
    float w0 = vals[e0], w1 = vals[e1];
    int   c0 = cols[e0], c1 = cols[e1];
    int   r0 = rows[e0], r1 = rows[e1];

    bool k0 = (u0 + 0.7f) >= 1.0f;   // matches reference f32 exactly
    bool k1 = (u1 + 0.7f) >= 1.0f;
    float v0 = (w0 / 0.7f) * scale;
    float v1 = (w1 / 0.7f) * scale;

    float4 a0, a1, b0, b1;
    const float4* s0 = (const float4*)(x + (size_t)c0 * DD);
    const float4* s1 = (const float4*)(x + (size_t)c1 * DD);
    if (k0) { a0 = s0[lane]; a1 = s0[lane + 8]; }
    if (k1) { b0 = s1[lane]; b1 = s1[lane + 8]; }

    if (k0) {
        float* d0 = out + (size_t)r0 * DD;
        red_add_v4(d0 + lane * 4,       v0 * a0.x, v0 * a0.y, v0 * a0.z, v0 * a0.w);
        red_add_v4(d0 + (lane + 8) * 4, v0 * a1.x, v0 * a1.y, v0 * a1.z, v0 * a1.w);
    }
    if (k1) {
        float* d1 = out + (size_t)r1 * DD;
        red_add_v4(d1 + lane * 4,       v1 * b0.x, v1 * b0.y, v1 * b0.z, v1 * b0.w);
        red_add_v4(d1 + (lane + 8) * 4, v1 * b1.x, v1 * b1.y, v1 * b1.z, v1 * b1.w);
    }
}

// Kernel A: blocks [0,FC_BLOCKS) compute out = (emb@W^T + b)/3 (plain store,
// sole writer of out in this launch); blocks [FC_BLOCKS, ...) do spmm0 into x1.
__global__ void __launch_bounds__(256)
kernelA(const float* __restrict__ emb,
        const float* __restrict__ W,
        const float* __restrict__ b,
        const float* __restrict__ vals,
        const float* __restrict__ du,
        const int*   __restrict__ rows,
        const int*   __restrict__ cols,
        float*       __restrict__ x1,
        float*       __restrict__ out) {
    if (blockIdx.x >= FC_BLOCKS) {
        spmm_body(emb, vals, du, rows, cols, x1, 1.0f,
                  blockIdx.x - FC_BLOCKS);
        return;
    }

    // ---- fc-GEMM path (R12 tile, 256 threads, no x1 term) ----
    __shared__ float est[DD][66];   // [k][node], pad 2 (8B-aligned LDS.64)
    __shared__ float Wt[DD][68];    // [k][col], 16B-aligned LDS.128

    int tid = threadIdx.x;          // 0..255
    int ng  = tid >> 4;             // pair group 0..15 (pairs ng, ng+16)
    int cg  = tid & 15;             // cols 4*cg..4*cg+3

    #pragma unroll
    for (int i = tid; i < DD * DD; i += 256) {
        int c = i >> 6;
        int k = i & 63;
        Wt[k][c] = W[c * DD + k];
    }

    int n0 = blockIdx.x * 64;
    #pragma unroll
    for (int i = tid; i < 64 * 16; i += 256) {
        int n  = i >> 4;
        int kq = i & 15;
        float4 v = make_float4(0.f, 0.f, 0.f, 0.f);
        if (n0 + n < NN) v = ((const float4*)emb)[(size_t)(n0 + n) * 16 + kq];
        est[4 * kq + 0][n] = v.x;
        est[4 * kq + 1][n] = v.y;
        est[4 * kq + 2][n] = v.z;
        est[4 * kq + 3][n] = v.w;
    }
    __syncthreads();

    unsigned long long acc[2][4];
    {
        float4 bv = *(const float4*)(b + 4 * cg);
        unsigned long long b0 = pk2(bv.x, bv.x);
        unsigned long long b1 = pk2(bv.y, bv.y);
        unsigned long long b2 = pk2(bv.z, bv.z);
        unsigned long long b3 = pk2(bv.w, bv.w);
        #pragma unroll
        for (int i = 0; i < 2; i++) {
            acc[i][0] = b0; acc[i][1] = b1; acc[i][2] = b2; acc[i][3] = b3;
        }
    }

    #pragma unroll 8
    for (int k = 0; k < DD; k++) {
        unsigned long long ap0 = *(const unsigned long long*)&est[k][2 * ng];
        unsigned long long ap1 = *(const unsigned long long*)&est[k][2 * (ng + 16)];
        float4 wv = *(const float4*)&Wt[k][4 * cg];
        unsigned long long wd0 = pk2(wv.x, wv.x);
        unsigned long long wd1 = pk2(wv.y, wv.y);
        unsigned long long wd2 = pk2(wv.z, wv.z);
        unsigned long long wd3 = pk2(wv.w, wv.w);
        ffma2(acc[0][0], ap0, wd0);
        ffma2(acc[0][1], ap0, wd1);
        ffma2(acc[0][2], ap0, wd2);
        ffma2(acc[0][3], ap0, wd3);
        ffma2(acc[1][0], ap1, wd0);
        ffma2(acc[1][1], ap1, wd1);
        ffma2(acc[1][2], ap1, wd2);
        ffma2(acc[1][3], ap1, wd3);
    }

    #pragma unroll
    for (int i = 0; i < 2; i++) {
        float lo0, hi0, lo1, hi1, lo2, hi2, lo3, hi3;
        upk2(lo0, hi0, acc[i][0]);
        upk2(lo1, hi1, acc[i][1]);
        upk2(lo2, hi2, acc[i][2]);
        upk2(lo3, hi3, acc[i][3]);
        int nbase = n0 + 2 * (ng + 16 * i);
        if (nbase < NN) {
            size_t idx = (size_t)nbase * 16 + cg;
            float4 o;
            o.x = lo0 * (1.0f / 3.0f);
            o.y = lo1 * (1.0f / 3.0f);
            o.z = lo2 * (1.0f / 3.0f);
            o.w = lo3 * (1.0f / 3.0f);
            ((float4*)out)[idx] = o;
        }
        if (nbase + 1 < NN) {
            size_t idx = (size_t)(nbase + 1) * 16 + cg;
            float4 o;
            o.x = hi0 * (1.0f / 3.0f);
            o.y = hi1 * (1.0f / 3.0f);
            o.z = hi2 * (1.0f / 3.0f);
            o.w = hi3 * (1.0f / 3.0f);
            ((float4*)out)[idx] = o;
        }
    }
}

// Kernel B: blocks [0,ADD_BLOCKS) red-add x1/3 into out; the rest do
// spmm1 (gather x1, red (A2@x1)/3 into out). All writers atomic -> race-free.
__global__ void __launch_bounds__(256)
kernelB(const float* __restrict__ x1,
        const float* __restrict__ vals,
        const float* __restrict__ du2,
        const int*   __restrict__ rows,
        const int*   __restrict__ cols,
        float*       __restrict__ out) {
    if (blockIdx.x < ADD_BLOCKS) {
        int i = blockIdx.x * 256 + threadIdx.x;     // < NN*DD/4 exactly
        float4 xv = ((const float4*)x1)[i];
        red_add_v4(out + (size_t)i * 4,
                   xv.x * (1.0f / 3.0f), xv.y * (1.0f / 3.0f),
                   xv.z * (1.0f / 3.0f), xv.w * (1.0f / 3.0f));
        return;
    }
    spmm_body(x1, vals, du2, rows, cols, out, 1.0f / 3.0f,
              blockIdx.x - ADD_BLOCKS);
}

extern "C" void kernel_launch(void* const* d_in, const int* in_sizes, int n_in,
                              void* d_out, int out_size) {
    const float* emb  = (const float*)d_in[0];
    const float* W    = (const float*)d_in[1];
    const float* b    = (const float*)d_in[2];
    const float* vals = (const float*)d_in[3];
    const float* du   = (const float*)d_in[4];   // [2, E]
    const int*   rows = (const int*)d_in[5];
    const int*   cols = (const int*)d_in[6];
    float* out = (float*)d_out;

    float* x1 = nullptr;
    cudaGetSymbolAddress((void**)&x1, g_x1);

    // 1) x1 = 0
    int n4 = NN * DD / 4;
    zero_kernel<<<(n4 + 255) / 256, 256>>>(x1, n4);

    // 2) fused: out = (emb@W^T + b)/3  (plain store)  ||  x1 += A1 @ emb
    kernelA<<<FC_BLOCKS + SP_BLOCKS, 256>>>(emb, W, b, vals, du, rows, cols,
                                            x1, out);

    // 3) fused: out += x1/3 (red)  ||  out += (A2 @ x1)/3 (red)
    kernelB<<<ADD_BLOCKS + SP_BLOCKS, 256>>>(x1, vals, du + NE, rows, cols,
                                             out);
}